// round 10
// baseline (speedup 1.0000x reference)
#include <cuda_runtime.h>
#include <cstdint>

#define NHEADS 8
#define NV     25
#define CI     64
#define NBATCH 32
#define TT     256
#define DF     1600
#define MR     (NBATCH*TT)   /* 8192 */
#define NPADW  1664          /* padded to 13*128 */

// ---------------- scratch (static device globals; no allocs allowed) --------
__device__ float g_xf[MR*DF];                  // packed x, tf32, shuffled
__device__ float g_mf[MR*DF];                  // packed m, tf32, shuffled
__device__ float g_Wt[24*NPADW*DF];            // K-major weights, tf32, shuffled
__device__ float g_Qs[NHEADS*MR*DF];           // queries [z=n*8+h][q][shuf(d)] tf32
__device__ float g_Ks[NHEADS*MR*DF];           // keys    same layout
__device__ float g_Vp[NHEADS*MR*DF];           // values  [h][m][d] plain fp32
__device__ float g_Vts[256*NPADW*TT];          // V^T [h*32+n][d(pad)][shuf(t)] tf32
__device__ float g_Sp[NBATCH*NHEADS*TT*TT];    // scores [z][q][t] fp32
__device__ float g_As[256*TT*TT];              // softmaxed att [z][q][shuf(t)] tf32

// ======================= helpers ===========================================
__device__ __forceinline__ float tf32r(float x) {
    uint32_t u;
    asm("cvt.rna.tf32.f32 %0, %1;" : "=r"(u) : "f"(x));
    return __uint_as_float(u);
}
// fragment-shuffled position of k within a row with parity row7 = row&7
__device__ __forceinline__ int shufpos(int k, int row7) {
    int chunk = k >> 5, kk = k & 31;
    int tig = kk & 3, j = kk >> 2;
    int slot = ((tig << 2) + (j >> 1)) ^ row7;
    return (chunk << 5) + (slot << 1) + (j & 1);
}
__device__ __forceinline__ void cp16(uint32_t dst, const float* src) {
    asm volatile("cp.async.cg.shared.global [%0], [%1], 16;"
                 :: "r"(dst), "l"(__cvta_generic_to_global(src)) : "memory");
}
__device__ __forceinline__ uint2 lds64(uint32_t addr) {
    uint2 r;
    asm volatile("ld.shared.v2.b32 {%0,%1}, [%2];" : "=r"(r.x), "=r"(r.y) : "r"(addr));
    return r;
}
__device__ __forceinline__ void mma8(float* c, uint32_t a0, uint32_t a1,
                                     uint32_t a2, uint32_t a3,
                                     uint32_t b0, uint32_t b1) {
    asm volatile("mma.sync.aligned.m16n8k8.row.col.f32.tf32.tf32.f32 "
                 "{%0,%1,%2,%3}, {%4,%5,%6,%7}, {%8,%9}, {%0,%1,%2,%3};"
                 : "+f"(c[0]), "+f"(c[1]), "+f"(c[2]), "+f"(c[3])
                 : "r"(a0), "r"(a1), "r"(a2), "r"(a3), "r"(b0), "r"(b1));
}

// ======================= shared tf32 GEMM mainloop ==========================
// CTA tile 256(M) x 128(N), 8 warps as 4(m) x 2(n), warp tile 64x64.
#define PST 3
#define STB 49152            /* A 32KB + B 16KB per stage */
#define SMEM_DYN (PST*STB)

template<int CH>
__device__ __forceinline__ void mm_mainloop(const float* tileA, int ldA,
                                            const float* tileB, int ldB,
                                            uint32_t smemBase, int tid,
                                            float (&acc)[4][8][4]) {
    const int lane = tid & 31, w = tid >> 5;
    const int g = lane >> 2, tig = lane & 3;
    const int wm = w & 3, wn = w >> 2;

    // producers: A row = tid (256 rows, 8x cp16); B row = tid&127, half = tid>>7
    const float* pA0 = tileA + (size_t)tid * ldA;
    const float* pB0 = tileB + (size_t)(tid & 127) * ldB + (tid >> 7) * 16;
    const uint32_t dA0 = smemBase + tid * 128;
    const uint32_t dB0 = smemBase + 32768 + (tid & 127) * 128 + (tid >> 7) * 64;

#define LS(s, j) do {                                                          \
        uint32_t dA = dA0 + (s) * STB; const float* pA = pA0 + (j) * 32;       \
        cp16(dA,      pA);      cp16(dA + 16,  pA + 4);                        \
        cp16(dA + 32, pA + 8);  cp16(dA + 48,  pA + 12);                       \
        cp16(dA + 64, pA + 16); cp16(dA + 80,  pA + 20);                       \
        cp16(dA + 96, pA + 24); cp16(dA + 112, pA + 28);                       \
        uint32_t dB = dB0 + (s) * STB; const float* pB = pB0 + (j) * 32;       \
        cp16(dB,      pB);      cp16(dB + 16,  pB + 4);                        \
        cp16(dB + 32, pB + 8);  cp16(dB + 48,  pB + 12);                       \
    } while (0)

    LS(0, 0);
    asm volatile("cp.async.commit_group;" ::: "memory");
    if (CH > 1) LS(1, 1);
    asm volatile("cp.async.commit_group;" ::: "memory");

    for (int j = 0; j < CH; j++) {
        asm volatile("cp.async.wait_group 1;" ::: "memory");
        __syncthreads();
        if (j + 2 < CH) LS((j + 2) % PST, j + 2);
        asm volatile("cp.async.commit_group;" ::: "memory");

        const uint32_t sA = smemBase + (j % PST) * STB;
        const uint32_t sB = sA + 32768;
#pragma unroll
        for (int jt = 0; jt < 4; jt++) {
            const int off = ((((tig << 2) + jt) ^ g) << 3);   // row&7 == g
            uint2 ap[8];
#pragma unroll
            for (int r = 0; r < 8; r++) {
                int row = wm * 64 + (r >> 1) * 16 + (r & 1) * 8 + g;
                ap[r] = lds64(sA + row * 128 + off);
            }
            uint2 bp[8];
#pragma unroll
            for (int nt = 0; nt < 8; nt++) {
                int n = wn * 64 + nt * 8 + g;
                bp[nt] = lds64(sB + n * 128 + off);
            }
#pragma unroll
            for (int mt = 0; mt < 4; mt++)
#pragma unroll
                for (int nt = 0; nt < 8; nt++)
                    mma8(acc[mt][nt],
                         ap[2 * mt].x, ap[2 * mt + 1].x,
                         ap[2 * mt].y, ap[2 * mt + 1].y,
                         bp[nt].x, bp[nt].y);
        }
    }
#undef LS
}

// ---------------- kernel 1: pack + tf32 round + shuffle ---------------------
__global__ void pack_kernel(const float* __restrict__ src, int sel) {
    int gid = blockIdx.x * blockDim.x + threadIdx.x;
    int r = gid / DF;
    int f = gid - r * DF;
    int n = r >> 8, t = r & 255;
    int c = f / NV, v = f - c * NV;
    float val = src[(((size_t)n * CI + c) * TT + t) * NV + v];
    float* dst = sel ? g_mf : g_xf;
    dst[(size_t)r * DF + shufpos(f, r & 7)] = tf32r(val);
}

// ---------------- kernel 1b: W[h][k][o] -> g_Wt[z][o][shuf(k)] --------------
__global__ void transpose_w(const float* __restrict__ Wk,
                            const float* __restrict__ Wq,
                            const float* __restrict__ Wv) {
    const int z = blockIdx.z;
    const int g = z >> 3, h = z & 7;
    const float* W = ((g == 0) ? Wk : (g == 1) ? Wq : Wv) + (size_t)h * DF * DF;
    float* Wt = g_Wt + (size_t)z * NPADW * DF;
    __shared__ float t[32][33];
    int k0 = blockIdx.x * 32, o0 = blockIdx.y * 32;
#pragma unroll
    for (int i = threadIdx.y; i < 32; i += 8)
        t[i][threadIdx.x] = W[(size_t)(k0 + i) * DF + o0 + threadIdx.x];
    __syncthreads();
#pragma unroll
    for (int i = threadIdx.y; i < 32; i += 8) {
        int o = o0 + i, k = k0 + threadIdx.x;
        Wt[(size_t)o * DF + shufpos(k, o & 7)] = tf32r(t[threadIdx.x][i]);
    }
}

// ---------------- kernel 2: projection GEMM (tf32 mma.sync) -----------------
// gg=0 -> K (shuffled), gg=1 -> Q (shuffled), gg=2 -> V (plain fp32)
__global__ __launch_bounds__(256, 1)
void gemm_proj_mma(const float* __restrict__ bk, const float* __restrict__ bq,
                   const float* __restrict__ bv) {
    extern __shared__ char dsm[];
    const uint32_t smemBase = (uint32_t)__cvta_generic_to_shared(dsm);
    const int tid = threadIdx.x;
    const int z = blockIdx.z, gg = z >> 3, h = z & 7;
    const int n0 = blockIdx.x * 128, m0 = blockIdx.y * 256;

    const float* A = (gg == 0) ? g_xf : g_mf;
    const float* B = g_Wt + (size_t)z * NPADW * DF;
    const float* bias = ((gg == 0) ? bk : (gg == 1) ? bq : bv) + (size_t)h * DF;

    float acc[4][8][4];
#pragma unroll
    for (int mt = 0; mt < 4; mt++)
#pragma unroll
        for (int nt = 0; nt < 8; nt++)
#pragma unroll
            for (int i = 0; i < 4; i++) acc[mt][nt][i] = 0.f;

    mm_mainloop<50>(A + (size_t)m0 * DF, DF, B + (size_t)n0 * DF, DF,
                    smemBase, tid, acc);

    const int lane = tid & 31, w = tid >> 5;
    const int g = lane >> 2, tig = lane & 3;
    const int wm = w & 3, wn = w >> 2;

    if (gg == 2) {
        float* C = g_Vp + (size_t)h * MR * DF;
#pragma unroll
        for (int mt = 0; mt < 4; mt++) {
            int row = m0 + wm * 64 + mt * 16 + g;
            float* c0 = C + (size_t)row * DF;
            float* c1 = C + (size_t)(row + 8) * DF;
#pragma unroll
            for (int nt = 0; nt < 8; nt++) {
                int col = n0 + wn * 64 + nt * 8 + tig * 2;
                if (col < DF) {
                    float b0v = bias[col], b1v = bias[col + 1];
                    *reinterpret_cast<float2*>(c0 + col) =
                        make_float2(acc[mt][nt][0] + b0v, acc[mt][nt][1] + b1v);
                    *reinterpret_cast<float2*>(c1 + col) =
                        make_float2(acc[mt][nt][2] + b0v, acc[mt][nt][3] + b1v);
                }
            }
        }
    } else {
        float* D = (gg == 0) ? g_Ks : g_Qs;
#pragma unroll
        for (int mt = 0; mt < 4; mt++) {
            int row = m0 + wm * 64 + mt * 16 + g;      // global m = n*256 + q
            int q  = row & 255;
            size_t b0r = ((size_t)(((row >> 8) << 3) + h) * 256 + q) * DF;
            size_t b1r = b0r + 8 * (size_t)DF;          // row+8: same n-block
#pragma unroll
            for (int nt = 0; nt < 8; nt++) {
                int col = n0 + wn * 64 + nt * 8 + tig * 2;
                if (col < DF) {
                    float b0v = bias[col], b1v = bias[col + 1];
                    int s0 = shufpos(col, q & 7), s1 = shufpos(col + 1, q & 7);
                    D[b0r + s0] = tf32r(acc[mt][nt][0] + b0v);
                    D[b0r + s1] = tf32r(acc[mt][nt][1] + b1v);
                    D[b1r + s0] = tf32r(acc[mt][nt][2] + b0v);
                    D[b1r + s1] = tf32r(acc[mt][nt][3] + b1v);
                }
            }
        }
    }
}

// ---------------- kernel 2b: V -> V^T shuffled tf32 -------------------------
__global__ void transpose_v() {
    const int z = blockIdx.z;                 // h*32 + n
    const int h = z >> 5, n = z & 31;
    const int t0 = blockIdx.x * 32, d0 = blockIdx.y * 32;
    __shared__ float tl[32][33];
    const float* Vp = g_Vp + (size_t)h * MR * DF + (size_t)(n * 256) * DF;
#pragma unroll
    for (int i = threadIdx.y; i < 32; i += 8)
        tl[i][threadIdx.x] = Vp[(size_t)(t0 + i) * DF + d0 + threadIdx.x];
    __syncthreads();
    float* Vt = g_Vts + (size_t)z * NPADW * TT;
#pragma unroll
    for (int i = threadIdx.y; i < 32; i += 8) {
        int d = d0 + i, t = t0 + threadIdx.x;
        Vt[(size_t)d * TT + shufpos(t, d & 7)] = tf32r(tl[threadIdx.x][i]);
    }
}

// ---------------- kernel 3: scores S = scale * Q K^T (tf32 mma) -------------
__global__ __launch_bounds__(256, 1)
void gemm_scores_mma() {
    extern __shared__ char dsm[];
    const uint32_t smemBase = (uint32_t)__cvta_generic_to_shared(dsm);
    const int tid = threadIdx.x;
    const int z = blockIdx.z;
    const int n0 = blockIdx.x * 128, m0 = blockIdx.y * 256;

    const float* tileA = g_Qs + ((size_t)z * 256 + m0) * DF;
    const float* tileB = g_Ks + ((size_t)z * 256 + n0) * DF;

    float acc[4][8][4];
#pragma unroll
    for (int mt = 0; mt < 4; mt++)
#pragma unroll
        for (int nt = 0; nt < 8; nt++)
#pragma unroll
            for (int i = 0; i < 4; i++) acc[mt][nt][i] = 0.f;

    mm_mainloop<50>(tileA, DF, tileB, DF, smemBase, tid, acc);

    const int lane = tid & 31, w = tid >> 5;
    const int g = lane >> 2, tig = lane & 3;
    const int wm = w & 3, wn = w >> 2;
    const float scale = 0.025f;
    float* Sc = g_Sp + (size_t)z * TT * TT;
#pragma unroll
    for (int mt = 0; mt < 4; mt++) {
        int q = m0 + wm * 64 + mt * 16 + g;
#pragma unroll
        for (int nt = 0; nt < 8; nt++) {
            int t = n0 + wn * 64 + nt * 8 + tig * 2;
            *reinterpret_cast<float2*>(Sc + (size_t)q * TT + t) =
                make_float2(acc[mt][nt][0] * scale, acc[mt][nt][1] * scale);
            *reinterpret_cast<float2*>(Sc + (size_t)(q + 8) * TT + t) =
                make_float2(acc[mt][nt][2] * scale, acc[mt][nt][3] * scale);
        }
    }
}

// ---------------- kernel 4: softmax over HEADS, fused shuffle+tf32 ----------
__global__ void softmax_heads() {
    int gid = blockIdx.x * blockDim.x + threadIdx.x;   // over NBATCH*T*T
    int n  = gid >> 16;
    int qt = gid & 65535;
    int q = qt >> 8, t = qt & 255;
    size_t base = ((size_t)(n * NHEADS) << 16) + qt;
    float v[NHEADS];
    float mx = -1e30f;
#pragma unroll
    for (int h = 0; h < NHEADS; h++) {
        v[h] = g_Sp[base + ((size_t)h << 16)];
        mx = fmaxf(mx, v[h]);
    }
    float s = 0.f;
#pragma unroll
    for (int h = 0; h < NHEADS; h++) { v[h] = __expf(v[h] - mx); s += v[h]; }
    float inv = 1.f / s;
    int sp = shufpos(t, q & 7);
#pragma unroll
    for (int h = 0; h < NHEADS; h++)
        g_As[((size_t)((n * NHEADS + h) * 256 + q) << 8) + sp] = tf32r(v[h] * inv);
}

// ---------------- kernel 5: Y = att @ V (tf32 mma), permuted store ----------
__global__ __launch_bounds__(256, 1)
void gemm_y_mma(float* __restrict__ out) {
    extern __shared__ char dsm[];
    const uint32_t smemBase = (uint32_t)__cvta_generic_to_shared(dsm);
    const int tid = threadIdx.x;
    const int z = blockIdx.z;
    const int n = z >> 3, h = z & 7;
    const int n0 = blockIdx.x * 128, m0 = blockIdx.y * 256;

    const float* tileA = g_As + ((size_t)z * 256 + m0) * TT;
    const float* tileB = g_Vts + ((size_t)(h * 32 + n) * NPADW + n0) * TT;

    float acc[4][8][4];
#pragma unroll
    for (int mt = 0; mt < 4; mt++)
#pragma unroll
        for (int nt = 0; nt < 8; nt++)
#pragma unroll
            for (int i = 0; i < 4; i++) acc[mt][nt][i] = 0.f;

    mm_mainloop<8>(tileA, TT, tileB, TT, smemBase, tid, acc);

    const int lane = tid & 31, w = tid >> 5;
    const int g = lane >> 2, tig = lane & 3;
    const int wm = w & 3, wn = w >> 2;
#pragma unroll
    for (int mt = 0; mt < 4; mt++) {
        int q = m0 + wm * 64 + mt * 16 + g;
#pragma unroll
        for (int nt = 0; nt < 8; nt++) {
            int d = n0 + wn * 64 + nt * 8 + tig * 2;
            if (d < DF) {
                int v = d >> 6;          // d = v*64 + c
                int c = d & 63;          // even
                size_t o = (size_t)n * (512 * TT * NV)
                         + (size_t)((c << 3) + h) * (TT * NV)
                         + (size_t)q * NV + v;
                size_t o2 = o + 8 * TT * NV;          // c+1
                out[o]                = acc[mt][nt][0];
                out[o2]               = acc[mt][nt][1];
                out[o + 8 * NV]       = acc[mt][nt][2];   // q+8
                out[o2 + 8 * NV]      = acc[mt][nt][3];
            }
        }
    }
}

// ---------------- launch ----------------------------------------------------
extern "C" void kernel_launch(void* const* d_in, const int* in_sizes, int n_in,
                              void* d_out, int out_size) {
    const float* x  = (const float*)d_in[0];
    const float* m  = (const float*)d_in[1];
    const float* Wk = (const float*)d_in[2];
    const float* bk = (const float*)d_in[3];
    const float* Wq = (const float*)d_in[4];
    const float* bq = (const float*)d_in[5];
    const float* Wv = (const float*)d_in[6];
    const float* bv = (const float*)d_in[7];
    float* out = (float*)d_out;

    cudaFuncSetAttribute(gemm_proj_mma,   cudaFuncAttributeMaxDynamicSharedMemorySize, SMEM_DYN);
    cudaFuncSetAttribute(gemm_scores_mma, cudaFuncAttributeMaxDynamicSharedMemorySize, SMEM_DYN);
    cudaFuncSetAttribute(gemm_y_mma,      cudaFuncAttributeMaxDynamicSharedMemorySize, SMEM_DYN);

    pack_kernel<<<(MR * DF) / 256, 256>>>(x, 0);
    pack_kernel<<<(MR * DF) / 256, 256>>>(m, 1);
    transpose_w<<<dim3(50, 50, 24), dim3(32, 8)>>>(Wk, Wq, Wv);

    // tf32 projections: CTA 256Mx128N -> grid (13, 32, 24)
    gemm_proj_mma<<<dim3(13, 32, 24), 256, SMEM_DYN>>>(bk, bq, bv);
    transpose_v<<<dim3(8, 50, 256), dim3(32, 8)>>>();

    gemm_scores_mma<<<dim3(2, 1, 256), 256, SMEM_DYN>>>();
    softmax_heads<<<(NBATCH * TT * TT) / 256, 256>>>();
    gemm_y_mma<<<dim3(13, 1, 256), 256, SMEM_DYN>>>(out);
}

// round 11
// speedup vs baseline: 1.2721x; 1.2721x over previous
#include <cuda_runtime.h>
#include <cstdint>

#define NHEADS 8
#define NV     25
#define CI     64
#define NBATCH 32
#define TT     256
#define DF     1600
#define MR     (NBATCH*TT)   /* 8192 */
#define NPADW  1664          /* padded to 13*128 */

// ---------------- scratch (static device globals; no allocs allowed) --------
__device__ float g_xf[MR*DF];                  // packed x, tf32, shuffled
__device__ float g_mf[MR*DF];                  // packed m, tf32, shuffled
__device__ float g_Wt[24*NPADW*DF];            // K-major weights, tf32, shuffled
__device__ float g_Qs[NHEADS*MR*DF];           // queries [z=n*8+h][q][shuf(d)] tf32
__device__ float g_Ks[NHEADS*MR*DF];           // keys    same layout
__device__ float g_Vp[NHEADS*MR*DF];           // values  [h][m][d] plain fp32
__device__ float g_Vts[256*NPADW*TT];          // V^T [h*32+n][d(pad)][shuf(t)] tf32
__device__ float g_Sp[NBATCH*NHEADS*TT*TT];    // scores [z][q][t] fp32
__device__ float g_As[256*TT*TT];              // softmaxed att [z][q][shuf(t)] tf32

// ======================= helpers ===========================================
__device__ __forceinline__ float tf32r(float x) {
    uint32_t u;
    asm("cvt.rna.tf32.f32 %0, %1;" : "=r"(u) : "f"(x));
    return __uint_as_float(u);
}
// fragment-shuffled position of k within a row with parity row7 = row&7
__device__ __forceinline__ int shufpos(int k, int row7) {
    int chunk = k >> 5, kk = k & 31;
    int tig = kk & 3, j = kk >> 2;
    int slot = ((tig << 2) + (j >> 1)) ^ row7;
    return (chunk << 5) + (slot << 1) + (j & 1);
}
__device__ __forceinline__ void cp16(uint32_t dst, const float* src) {
    asm volatile("cp.async.cg.shared.global [%0], [%1], 16;"
                 :: "r"(dst), "l"(__cvta_generic_to_global(src)) : "memory");
}
// NOTE: deliberately NOT volatile — lets ptxas interleave fragment loads with
// the MMA stream (software pipelining across jt). Shared-mem hazards are
// fenced by __syncthreads(), which is a full compiler memory barrier.
__device__ __forceinline__ uint2 lds64(uint32_t addr) {
    uint2 r;
    asm("ld.shared.v2.b32 {%0,%1}, [%2];" : "=r"(r.x), "=r"(r.y) : "r"(addr));
    return r;
}
__device__ __forceinline__ void mma8(float* c, uint32_t a0, uint32_t a1,
                                     uint32_t a2, uint32_t a3,
                                     uint32_t b0, uint32_t b1) {
    asm volatile("mma.sync.aligned.m16n8k8.row.col.f32.tf32.tf32.f32 "
                 "{%0,%1,%2,%3}, {%4,%5,%6,%7}, {%8,%9}, {%0,%1,%2,%3};"
                 : "+f"(c[0]), "+f"(c[1]), "+f"(c[2]), "+f"(c[3])
                 : "r"(a0), "r"(a1), "r"(a2), "r"(a3), "r"(b0), "r"(b1));
}

// ======================= shared tf32 GEMM mainloop ==========================
// CTA tile 128(M) x 128(N), 8 warps as 4(m) x 2(n), warp tile 32x64.
#define PST 3
#define STB 32768            /* A 16KB + B 16KB per stage */
#define SMEM_DYN (PST*STB)

__device__ __forceinline__ void load_stage(uint32_t smemBase, int s, int j,
                                           const float* pA0, const float* pB0,
                                           int arow, int ac) {
    uint32_t dA = smemBase + s * STB + arow * 128 + ac;
    const float* pA = pA0 + j * 32;
    const float* pB = pB0 + j * 32;
    cp16(dA,      pA);     cp16(dA + 16, pA + 4);
    cp16(dA + 32, pA + 8); cp16(dA + 48, pA + 12);
    uint32_t dB = dA + 16384;
    cp16(dB,      pB);     cp16(dB + 16, pB + 4);
    cp16(dB + 32, pB + 8); cp16(dB + 48, pB + 12);
}

template<int CH>
__device__ __forceinline__ void mm_mainloop(const float* tileA, int ldA,
                                            const float* tileB, int ldB,
                                            uint32_t smemBase, int tid,
                                            float (&acc)[2][8][4]) {
    const int lane = tid & 31, w = tid >> 5;
    const int g = lane >> 2, tig = lane & 3;
    const int wm = w & 3, wn = w >> 2;
    const int arow = tid >> 1, ac = (tid & 1) * 64;
    const float* pA0 = tileA + (size_t)arow * ldA + (ac >> 2);
    const float* pB0 = tileB + (size_t)arow * ldB + (ac >> 2);

    load_stage(smemBase, 0, 0, pA0, pB0, arow, ac);
    asm volatile("cp.async.commit_group;" ::: "memory");
    if (CH > 1) load_stage(smemBase, 1, 1, pA0, pB0, arow, ac);
    asm volatile("cp.async.commit_group;" ::: "memory");

    for (int j = 0; j < CH; j++) {
        asm volatile("cp.async.wait_group 1;" ::: "memory");
        __syncthreads();
        if (j + 2 < CH) load_stage(smemBase, (j + 2) % PST, j + 2, pA0, pB0, arow, ac);
        asm volatile("cp.async.commit_group;" ::: "memory");

        const uint32_t sA = smemBase + (j % PST) * STB;
        const uint32_t sB = sA + 16384;
#pragma unroll
        for (int jt = 0; jt < 4; jt++) {
            uint2 ap[4];
#pragma unroll
            for (int r = 0; r < 4; r++) {
                int row = wm * 32 + (r & 1) * 8 + (r >> 1) * 16 + g;
                int off = ((((tig << 2) + jt) ^ (row & 7)) << 3);
                ap[r] = lds64(sA + row * 128 + off);
            }
            uint2 bp[8];
#pragma unroll
            for (int nt = 0; nt < 8; nt++) {
                int n = wn * 64 + nt * 8 + g;
                int off = ((((tig << 2) + jt) ^ (n & 7)) << 3);
                bp[nt] = lds64(sB + n * 128 + off);
            }
#pragma unroll
            for (int mt = 0; mt < 2; mt++)
#pragma unroll
                for (int nt = 0; nt < 8; nt++)
                    mma8(acc[mt][nt],
                         ap[2 * mt].x, ap[2 * mt + 1].x,
                         ap[2 * mt].y, ap[2 * mt + 1].y,
                         bp[nt].x, bp[nt].y);
        }
    }
}

// ---------------- kernel 1: pack + tf32 round + shuffle ---------------------
__global__ void pack_kernel(const float* __restrict__ src, int sel) {
    int gid = blockIdx.x * blockDim.x + threadIdx.x;
    int r = gid / DF;
    int f = gid - r * DF;
    int n = r >> 8, t = r & 255;
    int c = f / NV, v = f - c * NV;
    float val = src[(((size_t)n * CI + c) * TT + t) * NV + v];
    float* dst = sel ? g_mf : g_xf;
    dst[(size_t)r * DF + shufpos(f, r & 7)] = tf32r(val);
}

// ---------------- kernel 1b: W[h][k][o] -> g_Wt[z][o][shuf(k)] --------------
__global__ void transpose_w(const float* __restrict__ Wk,
                            const float* __restrict__ Wq,
                            const float* __restrict__ Wv) {
    const int z = blockIdx.z;
    const int g = z >> 3, h = z & 7;
    const float* W = ((g == 0) ? Wk : (g == 1) ? Wq : Wv) + (size_t)h * DF * DF;
    float* Wt = g_Wt + (size_t)z * NPADW * DF;
    __shared__ float t[32][33];
    int k0 = blockIdx.x * 32, o0 = blockIdx.y * 32;
#pragma unroll
    for (int i = threadIdx.y; i < 32; i += 8)
        t[i][threadIdx.x] = W[(size_t)(k0 + i) * DF + o0 + threadIdx.x];
    __syncthreads();
#pragma unroll
    for (int i = threadIdx.y; i < 32; i += 8) {
        int o = o0 + i, k = k0 + threadIdx.x;
        Wt[(size_t)o * DF + shufpos(k, o & 7)] = tf32r(t[threadIdx.x][i]);
    }
}

// ---------------- kernel 2: projection GEMM (tf32 mma.sync) -----------------
// gg=0 -> K (shuffled), gg=1 -> Q (shuffled), gg=2 -> V (plain fp32)
__global__ __launch_bounds__(256, 2)
void gemm_proj_mma(const float* __restrict__ bk, const float* __restrict__ bq,
                   const float* __restrict__ bv) {
    extern __shared__ char dsm[];
    const uint32_t smemBase = (uint32_t)__cvta_generic_to_shared(dsm);
    const int tid = threadIdx.x;
    const int z = blockIdx.z, gg = z >> 3, h = z & 7;
    const int n0 = blockIdx.x * 128, m0 = blockIdx.y * 128;

    const float* A = (gg == 0) ? g_xf : g_mf;
    const float* B = g_Wt + (size_t)z * NPADW * DF;
    const float* bias = ((gg == 0) ? bk : (gg == 1) ? bq : bv) + (size_t)h * DF;

    float acc[2][8][4];
#pragma unroll
    for (int mt = 0; mt < 2; mt++)
#pragma unroll
        for (int nt = 0; nt < 8; nt++)
#pragma unroll
            for (int i = 0; i < 4; i++) acc[mt][nt][i] = 0.f;

    mm_mainloop<50>(A + (size_t)m0 * DF, DF, B + (size_t)n0 * DF, DF,
                    smemBase, tid, acc);

    const int lane = tid & 31, w = tid >> 5;
    const int g = lane >> 2, tig = lane & 3;
    const int wm = w & 3, wn = w >> 2;

    if (gg == 2) {
        float* C = g_Vp + (size_t)h * MR * DF;
#pragma unroll
        for (int mt = 0; mt < 2; mt++) {
            int row = m0 + wm * 32 + mt * 16 + g;
            float* c0 = C + (size_t)row * DF;
            float* c1 = C + (size_t)(row + 8) * DF;
#pragma unroll
            for (int nt = 0; nt < 8; nt++) {
                int col = n0 + wn * 64 + nt * 8 + tig * 2;
                if (col < DF) {
                    float b0v = bias[col], b1v = bias[col + 1];
                    *reinterpret_cast<float2*>(c0 + col) =
                        make_float2(acc[mt][nt][0] + b0v, acc[mt][nt][1] + b1v);
                    *reinterpret_cast<float2*>(c1 + col) =
                        make_float2(acc[mt][nt][2] + b0v, acc[mt][nt][3] + b1v);
                }
            }
        }
    } else {
        float* D = (gg == 0) ? g_Ks : g_Qs;
#pragma unroll
        for (int mt = 0; mt < 2; mt++) {
            int row = m0 + wm * 32 + mt * 16 + g;      // global m = n*256 + q
            int q  = row & 255;
            size_t b0r = ((size_t)(((row >> 8) << 3) + h) * 256 + q) * DF;
            size_t b1r = b0r + 8 * (size_t)DF;          // row+8: same n-block
#pragma unroll
            for (int nt = 0; nt < 8; nt++) {
                int col = n0 + wn * 64 + nt * 8 + tig * 2;
                if (col < DF) {
                    float b0v = bias[col], b1v = bias[col + 1];
                    int s0 = shufpos(col, q & 7), s1 = shufpos(col + 1, q & 7);
                    D[b0r + s0] = tf32r(acc[mt][nt][0] + b0v);
                    D[b0r + s1] = tf32r(acc[mt][nt][1] + b1v);
                    D[b1r + s0] = tf32r(acc[mt][nt][2] + b0v);
                    D[b1r + s1] = tf32r(acc[mt][nt][3] + b1v);
                }
            }
        }
    }
}

// ---------------- kernel 2b: V -> V^T shuffled tf32 -------------------------
__global__ void transpose_v() {
    const int z = blockIdx.z;                 // h*32 + n
    const int h = z >> 5, n = z & 31;
    const int t0 = blockIdx.x * 32, d0 = blockIdx.y * 32;
    __shared__ float tl[32][33];
    const float* Vp = g_Vp + (size_t)h * MR * DF + (size_t)(n * 256) * DF;
#pragma unroll
    for (int i = threadIdx.y; i < 32; i += 8)
        tl[i][threadIdx.x] = Vp[(size_t)(t0 + i) * DF + d0 + threadIdx.x];
    __syncthreads();
    float* Vt = g_Vts + (size_t)z * NPADW * TT;
#pragma unroll
    for (int i = threadIdx.y; i < 32; i += 8) {
        int d = d0 + i, t = t0 + threadIdx.x;
        Vt[(size_t)d * TT + shufpos(t, d & 7)] = tf32r(tl[threadIdx.x][i]);
    }
}

// ---------------- kernel 3: scores S = scale * Q K^T (tf32 mma) -------------
__global__ __launch_bounds__(256, 2)
void gemm_scores_mma() {
    extern __shared__ char dsm[];
    const uint32_t smemBase = (uint32_t)__cvta_generic_to_shared(dsm);
    const int tid = threadIdx.x;
    const int z = blockIdx.z;
    const int n0 = blockIdx.x * 128, m0 = blockIdx.y * 128;

    const float* tileA = g_Qs + ((size_t)z * 256 + m0) * DF;
    const float* tileB = g_Ks + ((size_t)z * 256 + n0) * DF;

    float acc[2][8][4];
#pragma unroll
    for (int mt = 0; mt < 2; mt++)
#pragma unroll
        for (int nt = 0; nt < 8; nt++)
#pragma unroll
            for (int i = 0; i < 4; i++) acc[mt][nt][i] = 0.f;

    mm_mainloop<50>(tileA, DF, tileB, DF, smemBase, tid, acc);

    const int lane = tid & 31, w = tid >> 5;
    const int g = lane >> 2, tig = lane & 3;
    const int wm = w & 3, wn = w >> 2;
    const float scale = 0.025f;
    float* Sc = g_Sp + (size_t)z * TT * TT;
#pragma unroll
    for (int mt = 0; mt < 2; mt++) {
        int q = m0 + wm * 32 + mt * 16 + g;
#pragma unroll
        for (int nt = 0; nt < 8; nt++) {
            int t = n0 + wn * 64 + nt * 8 + tig * 2;
            *reinterpret_cast<float2*>(Sc + (size_t)q * TT + t) =
                make_float2(acc[mt][nt][0] * scale, acc[mt][nt][1] * scale);
            *reinterpret_cast<float2*>(Sc + (size_t)(q + 8) * TT + t) =
                make_float2(acc[mt][nt][2] * scale, acc[mt][nt][3] * scale);
        }
    }
}

// ---------------- kernel 4: softmax over HEADS, fused shuffle+tf32 ----------
__global__ void softmax_heads() {
    int gid = blockIdx.x * blockDim.x + threadIdx.x;   // over NBATCH*T*T
    int n  = gid >> 16;
    int qt = gid & 65535;
    int q = qt >> 8, t = qt & 255;
    size_t base = ((size_t)(n * NHEADS) << 16) + qt;
    float v[NHEADS];
    float mx = -1e30f;
#pragma unroll
    for (int h = 0; h < NHEADS; h++) {
        v[h] = g_Sp[base + ((size_t)h << 16)];
        mx = fmaxf(mx, v[h]);
    }
    float s = 0.f;
#pragma unroll
    for (int h = 0; h < NHEADS; h++) { v[h] = __expf(v[h] - mx); s += v[h]; }
    float inv = 1.f / s;
    int sp = shufpos(t, q & 7);
#pragma unroll
    for (int h = 0; h < NHEADS; h++)
        g_As[((size_t)((n * NHEADS + h) * 256 + q) << 8) + sp] = tf32r(v[h] * inv);
}

// ---------------- kernel 5: Y = att @ V (tf32 mma), permuted store ----------
__global__ __launch_bounds__(256, 2)
void gemm_y_mma(float* __restrict__ out) {
    extern __shared__ char dsm[];
    const uint32_t smemBase = (uint32_t)__cvta_generic_to_shared(dsm);
    const int tid = threadIdx.x;
    const int z = blockIdx.z;
    const int n = z >> 3, h = z & 7;
    const int n0 = blockIdx.x * 128, m0 = blockIdx.y * 128;

    const float* tileA = g_As + ((size_t)z * 256 + m0) * TT;
    const float* tileB = g_Vts + ((size_t)(h * 32 + n) * NPADW + n0) * TT;

    float acc[2][8][4];
#pragma unroll
    for (int mt = 0; mt < 2; mt++)
#pragma unroll
        for (int nt = 0; nt < 8; nt++)
#pragma unroll
            for (int i = 0; i < 4; i++) acc[mt][nt][i] = 0.f;

    mm_mainloop<8>(tileA, TT, tileB, TT, smemBase, tid, acc);

    const int lane = tid & 31, w = tid >> 5;
    const int g = lane >> 2, tig = lane & 3;
    const int wm = w & 3, wn = w >> 2;
#pragma unroll
    for (int mt = 0; mt < 2; mt++) {
        int q = m0 + wm * 32 + mt * 16 + g;
#pragma unroll
        for (int nt = 0; nt < 8; nt++) {
            int d = n0 + wn * 64 + nt * 8 + tig * 2;
            if (d < DF) {
                int v = d >> 6;          // d = v*64 + c
                int c = d & 63;          // even
                size_t o = (size_t)n * (512 * TT * NV)
                         + (size_t)((c << 3) + h) * (TT * NV)
                         + (size_t)q * NV + v;
                size_t o2 = o + 8 * TT * NV;          // c+1
                out[o]                = acc[mt][nt][0];
                out[o2]               = acc[mt][nt][1];
                out[o + 8 * NV]       = acc[mt][nt][2];   // q+8
                out[o2 + 8 * NV]      = acc[mt][nt][3];
            }
        }
    }
}

// ---------------- launch ----------------------------------------------------
extern "C" void kernel_launch(void* const* d_in, const int* in_sizes, int n_in,
                              void* d_out, int out_size) {
    const float* x  = (const float*)d_in[0];
    const float* m  = (const float*)d_in[1];
    const float* Wk = (const float*)d_in[2];
    const float* bk = (const float*)d_in[3];
    const float* Wq = (const float*)d_in[4];
    const float* bq = (const float*)d_in[5];
    const float* Wv = (const float*)d_in[6];
    const float* bv = (const float*)d_in[7];
    float* out = (float*)d_out;

    cudaFuncSetAttribute(gemm_proj_mma,   cudaFuncAttributeMaxDynamicSharedMemorySize, SMEM_DYN);
    cudaFuncSetAttribute(gemm_scores_mma, cudaFuncAttributeMaxDynamicSharedMemorySize, SMEM_DYN);
    cudaFuncSetAttribute(gemm_y_mma,      cudaFuncAttributeMaxDynamicSharedMemorySize, SMEM_DYN);

    pack_kernel<<<(MR * DF) / 256, 256>>>(x, 0);
    pack_kernel<<<(MR * DF) / 256, 256>>>(m, 1);
    transpose_w<<<dim3(50, 50, 24), dim3(32, 8)>>>(Wk, Wq, Wv);

    gemm_proj_mma<<<dim3(13, 64, 24), 256, SMEM_DYN>>>(bk, bq, bv);
    transpose_v<<<dim3(8, 50, 256), dim3(32, 8)>>>();

    gemm_scores_mma<<<dim3(2, 2, 256), 256, SMEM_DYN>>>();
    softmax_heads<<<(NBATCH * TT * TT) / 256, 256>>>();
    gemm_y_mma<<<dim3(13, 2, 256), 256, SMEM_DYN>>>(out);
}

// round 14
// speedup vs baseline: 1.4902x; 1.1714x over previous
#include <cuda_runtime.h>
#include <cuda_fp16.h>
#include <cstdint>

#define NHEADS 8
#define NV     25
#define CI     64
#define NBATCH 32
#define TT     256
#define DF     1600
#define MR     (NBATCH*TT)   /* 8192 */
#define NPADW  1664          /* padded to 13*128 */

// ---------------- scratch (static device globals; no allocs allowed) --------
__device__ __half g_xf[MR*DF];                  // packed x, fp16, shuffled
__device__ __half g_mf[MR*DF];                  // packed m, fp16, shuffled
__device__ __half g_Wt[24*NPADW*DF];            // K-major weights, fp16, shuffled
__device__ __half g_Qs[NHEADS*MR*DF];           // queries [z][q][shuf16(d)]
__device__ __half g_Ks[NHEADS*MR*DF];           // keys    same layout
__device__ float  g_Vp[NHEADS*MR*DF];           // values  [h][m][d] fp32
__device__ __half g_Vts[256*NPADW*TT];          // V^T [h*32+n][d(pad)][shuf16(t)]
__device__ float  g_Sp[NBATCH*NHEADS*TT*TT];    // scores [z][q][t] fp32
__device__ __half g_As[256*TT*TT];              // softmaxed att [z][q][shuf16(t)]

// ======================= helpers ===========================================
// fp16 fragment-shuffled position of half-index k in a row with parity row7.
// 64-halves (128B) chunk per stage-row; within each k16 group, 4 slots of 8B:
// slot tig holds halves [2tig, 2tig+1, 2tig+8, 2tig+9]; slot index
// (jt*4+tig) XOR row7 for bank-conflict-free lds64.
__device__ __forceinline__ int shufpos16(int k, int row7) {
    int chunk = k >> 6, kc = k & 63;
    int jt = kc >> 4, kk = kc & 15;
    int tig = (kk & 7) >> 1;
    int pos = (kk & 1) | ((kk >> 3) << 1);
    int slot = ((jt << 2) | tig) ^ row7;
    return (chunk << 6) + (slot << 2) + pos;
}
__device__ __forceinline__ void cp16(uint32_t dst, const void* src) {
    asm volatile("cp.async.cg.shared.global [%0], [%1], 16;"
                 :: "r"(dst), "l"(__cvta_generic_to_global(src)) : "memory");
}
__device__ __forceinline__ uint2 lds64(uint32_t addr) {
    uint2 r;
    asm("ld.shared.v2.b32 {%0,%1}, [%2];" : "=r"(r.x), "=r"(r.y) : "r"(addr));
    return r;
}
__device__ __forceinline__ void mma16(float* c, uint32_t a0, uint32_t a1,
                                      uint32_t a2, uint32_t a3,
                                      uint32_t b0, uint32_t b1) {
    asm volatile("mma.sync.aligned.m16n8k16.row.col.f32.f16.f16.f32 "
                 "{%0,%1,%2,%3}, {%4,%5,%6,%7}, {%8,%9}, {%0,%1,%2,%3};"
                 : "+f"(c[0]), "+f"(c[1]), "+f"(c[2]), "+f"(c[3])
                 : "r"(a0), "r"(a1), "r"(a2), "r"(a3), "r"(b0), "r"(b1));
}

// ======================= shared fp16 GEMM mainloop ==========================
// CTA tile 128(M) x 128(N), 8 warps as 4(m) x 2(n), warp tile 32x64.
// K-chunk per stage = 64 halves (128B per row).
#define PST 3
#define STB 32768            /* A 16KB + B 16KB per stage */
#define SMEM_DYN (PST*STB)

__device__ __forceinline__ void load_stage(uint32_t smemBase, int s, int j,
                                           const __half* pA0, const __half* pB0,
                                           int arow, int acB) {
    uint32_t dA = smemBase + s * STB + arow * 128 + acB;
    const __half* pA = pA0 + j * 64;
    const __half* pB = pB0 + j * 64;
    cp16(dA,      pA);      cp16(dA + 16, pA + 8);
    cp16(dA + 32, pA + 16); cp16(dA + 48, pA + 24);
    uint32_t dB = dA + 16384;
    cp16(dB,      pB);      cp16(dB + 16, pB + 8);
    cp16(dB + 32, pB + 16); cp16(dB + 48, pB + 24);
}

template<int CH>
__device__ __forceinline__ void mm_mainloop(const __half* tileA, int ldA,
                                            const __half* tileB, int ldB,
                                            uint32_t smemBase, int tid,
                                            float (&acc)[2][8][4]) {
    const int lane = tid & 31, w = tid >> 5;
    const int g = lane >> 2, tig = lane & 3;
    const int wm = w & 3, wn = w >> 2;
    const int arow = tid >> 1;
    const int acB  = (tid & 1) * 64;               // byte offset within 128B row
    const __half* pA0 = tileA + (size_t)arow * ldA + (acB >> 1);
    const __half* pB0 = tileB + (size_t)arow * ldB + (acB >> 1);

    load_stage(smemBase, 0, 0, pA0, pB0, arow, acB);
    asm volatile("cp.async.commit_group;" ::: "memory");
    if (CH > 1) load_stage(smemBase, 1, 1, pA0, pB0, arow, acB);
    asm volatile("cp.async.commit_group;" ::: "memory");

    for (int j = 0; j < CH; j++) {
        asm volatile("cp.async.wait_group 1;" ::: "memory");
        __syncthreads();
        if (j + 2 < CH) load_stage(smemBase, (j + 2) % PST, j + 2, pA0, pB0, arow, acB);
        asm volatile("cp.async.commit_group;" ::: "memory");

        const uint32_t sA = smemBase + (j % PST) * STB;
        const uint32_t sB = sA + 16384;
#pragma unroll
        for (int jt = 0; jt < 4; jt++) {
            const int soff = ((((jt << 2) | tig) ^ g) << 3);   // row&7 == g
            uint2 ar[4];                   // [mt*2 + {lo row, hi row}]
#pragma unroll
            for (int mt = 0; mt < 2; mt++) {
                int rbase = wm * 32 + mt * 16 + g;
                ar[2 * mt]     = lds64(sA + rbase * 128 + soff);        // a0,a2
                ar[2 * mt + 1] = lds64(sA + (rbase + 8) * 128 + soff);  // a1,a3
            }
            uint2 bp[8];
#pragma unroll
            for (int nt = 0; nt < 8; nt++) {
                int n = wn * 64 + nt * 8 + g;
                bp[nt] = lds64(sB + n * 128 + soff);
            }
#pragma unroll
            for (int mt = 0; mt < 2; mt++)
#pragma unroll
                for (int nt = 0; nt < 8; nt++)
                    mma16(acc[mt][nt],
                          ar[2 * mt].x, ar[2 * mt + 1].x,
                          ar[2 * mt].y, ar[2 * mt + 1].y,
                          bp[nt].x, bp[nt].y);
        }
    }
}

// ---------------- kernel 1: pack + fp16 round + shuffle ---------------------
__global__ void pack_kernel(const float* __restrict__ src, int sel) {
    int gid = blockIdx.x * blockDim.x + threadIdx.x;
    int r = gid / DF;
    int f = gid - r * DF;
    int n = r >> 8, t = r & 255;
    int c = f / NV, v = f - c * NV;
    float val = src[(((size_t)n * CI + c) * TT + t) * NV + v];
    __half* dst = sel ? g_mf : g_xf;
    dst[(size_t)r * DF + shufpos16(f, r & 7)] = __float2half_rn(val);
}

// ---------------- kernel 1b: W[h][k][o] -> g_Wt[z][o][shuf16(k)] ------------
__global__ void transpose_w(const float* __restrict__ Wk,
                            const float* __restrict__ Wq,
                            const float* __restrict__ Wv) {
    const int z = blockIdx.z;
    const int g = z >> 3, h = z & 7;
    const float* W = ((g == 0) ? Wk : (g == 1) ? Wq : Wv) + (size_t)h * DF * DF;
    __half* Wt = g_Wt + (size_t)z * NPADW * DF;
    __shared__ float t[32][33];
    int k0 = blockIdx.x * 32, o0 = blockIdx.y * 32;
#pragma unroll
    for (int i = threadIdx.y; i < 32; i += 8)
        t[i][threadIdx.x] = W[(size_t)(k0 + i) * DF + o0 + threadIdx.x];
    __syncthreads();
#pragma unroll
    for (int i = threadIdx.y; i < 32; i += 8) {
        int o = o0 + i, k = k0 + threadIdx.x;
        Wt[(size_t)o * DF + shufpos16(k, o & 7)] = __float2half_rn(t[threadIdx.x][i]);
    }
}

// ---------------- kernel 2: projection GEMM (fp16 mma.sync) -----------------
// gg=0 -> K (shuffled fp16), gg=1 -> Q (shuffled fp16), gg=2 -> V (fp32)
__global__ __launch_bounds__(256, 2)
void gemm_proj_mma(const float* __restrict__ bk, const float* __restrict__ bq,
                   const float* __restrict__ bv) {
    extern __shared__ char dsm[];
    const uint32_t smemBase = (uint32_t)__cvta_generic_to_shared(dsm);
    const int tid = threadIdx.x;
    const int z = blockIdx.z, gg = z >> 3, h = z & 7;
    const int n0 = blockIdx.x * 128, m0 = blockIdx.y * 128;

    const __half* A = (gg == 0) ? g_xf : g_mf;
    const __half* B = g_Wt + (size_t)z * NPADW * DF;
    const float* bias = ((gg == 0) ? bk : (gg == 1) ? bq : bv) + (size_t)h * DF;

    float acc[2][8][4];
#pragma unroll
    for (int mt = 0; mt < 2; mt++)
#pragma unroll
        for (int nt = 0; nt < 8; nt++)
#pragma unroll
            for (int i = 0; i < 4; i++) acc[mt][nt][i] = 0.f;

    mm_mainloop<25>(A + (size_t)m0 * DF, DF, B + (size_t)n0 * DF, DF,
                    smemBase, tid, acc);

    const int lane = tid & 31, w = tid >> 5;
    const int g = lane >> 2, tig = lane & 3;
    const int wm = w & 3, wn = w >> 2;

    if (gg == 2) {
        float* C = g_Vp + (size_t)h * MR * DF;
#pragma unroll
        for (int mt = 0; mt < 2; mt++) {
            int row = m0 + wm * 32 + mt * 16 + g;
            float* c0 = C + (size_t)row * DF;
            float* c1 = C + (size_t)(row + 8) * DF;
#pragma unroll
            for (int nt = 0; nt < 8; nt++) {
                int col = n0 + wn * 64 + nt * 8 + tig * 2;
                if (col < DF) {
                    float b0v = bias[col], b1v = bias[col + 1];
                    *reinterpret_cast<float2*>(c0 + col) =
                        make_float2(acc[mt][nt][0] + b0v, acc[mt][nt][1] + b1v);
                    *reinterpret_cast<float2*>(c1 + col) =
                        make_float2(acc[mt][nt][2] + b0v, acc[mt][nt][3] + b1v);
                }
            }
        }
    } else {
        __half* D = (gg == 0) ? g_Ks : g_Qs;
#pragma unroll
        for (int mt = 0; mt < 2; mt++) {
            int row = m0 + wm * 32 + mt * 16 + g;      // global m = n*256 + q
            int q  = row & 255;
            size_t b0r = ((size_t)(((row >> 8) << 3) + h) * 256 + q) * DF;
            size_t b1r = b0r + 8 * (size_t)DF;          // row+8: same parity
#pragma unroll
            for (int nt = 0; nt < 8; nt++) {
                int col = n0 + wn * 64 + nt * 8 + tig * 2;
                if (col < DF) {
                    float b0v = bias[col], b1v = bias[col + 1];
                    int s0 = shufpos16(col, q & 7);     // col even -> s0 even,
                                                        // col+1 lands at s0+1
                    *reinterpret_cast<__half2*>(&D[b0r + s0]) =
                        __floats2half2_rn(acc[mt][nt][0] + b0v, acc[mt][nt][1] + b1v);
                    *reinterpret_cast<__half2*>(&D[b1r + s0]) =
                        __floats2half2_rn(acc[mt][nt][2] + b0v, acc[mt][nt][3] + b1v);
                }
            }
        }
    }
}

// ---------------- kernel 2b: V -> V^T shuffled fp16 -------------------------
__global__ void transpose_v() {
    const int z = blockIdx.z;                 // h*32 + n
    const int h = z >> 5, n = z & 31;
    const int t0 = blockIdx.x * 32, d0 = blockIdx.y * 32;
    __shared__ float tl[32][33];
    const float* Vp = g_Vp + (size_t)h * MR * DF + (size_t)(n * 256) * DF;
#pragma unroll
    for (int i = threadIdx.y; i < 32; i += 8)
        tl[i][threadIdx.x] = Vp[(size_t)(t0 + i) * DF + d0 + threadIdx.x];
    __syncthreads();
    __half* Vt = g_Vts + (size_t)z * NPADW * TT;
#pragma unroll
    for (int i = threadIdx.y; i < 32; i += 8) {
        int d = d0 + i, t = t0 + threadIdx.x;
        Vt[(size_t)d * TT + shufpos16(t, d & 7)] = __float2half_rn(tl[threadIdx.x][i]);
    }
}

// ---------------- kernel 3: scores S = scale * Q K^T (fp16 mma) -------------
__global__ __launch_bounds__(256, 2)
void gemm_scores_mma() {
    extern __shared__ char dsm[];
    const uint32_t smemBase = (uint32_t)__cvta_generic_to_shared(dsm);
    const int tid = threadIdx.x;
    const int z = blockIdx.z;
    const int n0 = blockIdx.x * 128, m0 = blockIdx.y * 128;

    const __half* tileA = g_Qs + ((size_t)z * 256 + m0) * DF;
    const __half* tileB = g_Ks + ((size_t)z * 256 + n0) * DF;

    float acc[2][8][4];
#pragma unroll
    for (int mt = 0; mt < 2; mt++)
#pragma unroll
        for (int nt = 0; nt < 8; nt++)
#pragma unroll
            for (int i = 0; i < 4; i++) acc[mt][nt][i] = 0.f;

    mm_mainloop<25>(tileA, DF, tileB, DF, smemBase, tid, acc);

    const int lane = tid & 31, w = tid >> 5;
    const int g = lane >> 2, tig = lane & 3;
    const int wm = w & 3, wn = w >> 2;
    const float scale = 0.025f;
    float* Sc = g_Sp + (size_t)z * TT * TT;
#pragma unroll
    for (int mt = 0; mt < 2; mt++) {
        int q = m0 + wm * 32 + mt * 16 + g;
#pragma unroll
        for (int nt = 0; nt < 8; nt++) {
            int t = n0 + wn * 64 + nt * 8 + tig * 2;
            *reinterpret_cast<float2*>(Sc + (size_t)q * TT + t) =
                make_float2(acc[mt][nt][0] * scale, acc[mt][nt][1] * scale);
            *reinterpret_cast<float2*>(Sc + (size_t)(q + 8) * TT + t) =
                make_float2(acc[mt][nt][2] * scale, acc[mt][nt][3] * scale);
        }
    }
}

// ---------------- kernel 4: softmax over HEADS, fused shuffle+fp16 ----------
__global__ void softmax_heads() {
    int gid = blockIdx.x * blockDim.x + threadIdx.x;   // over NBATCH*T*T
    int n  = gid >> 16;
    int qt = gid & 65535;
    int q = qt >> 8, t = qt & 255;
    size_t base = ((size_t)(n * NHEADS) << 16) + qt;
    float v[NHEADS];
    float mx = -1e30f;
#pragma unroll
    for (int h = 0; h < NHEADS; h++) {
        v[h] = g_Sp[base + ((size_t)h << 16)];
        mx = fmaxf(mx, v[h]);
    }
    float s = 0.f;
#pragma unroll
    for (int h = 0; h < NHEADS; h++) { v[h] = __expf(v[h] - mx); s += v[h]; }
    float inv = 1.f / s;
    int sp = shufpos16(t, q & 7);
#pragma unroll
    for (int h = 0; h < NHEADS; h++)
        g_As[((size_t)((n * NHEADS + h) * 256 + q) << 8) + sp] =
            __float2half_rn(v[h] * inv);
}

// ---------------- kernel 5: Y = att @ V (fp16 mma), permuted store ----------
__global__ __launch_bounds__(256, 2)
void gemm_y_mma(float* __restrict__ out) {
    extern __shared__ char dsm[];
    const uint32_t smemBase = (uint32_t)__cvta_generic_to_shared(dsm);
    const int tid = threadIdx.x;
    const int z = blockIdx.z;
    const int n = z >> 3, h = z & 7;
    const int n0 = blockIdx.x * 128, m0 = blockIdx.y * 128;

    const __half* tileA = g_As + ((size_t)z * 256 + m0) * TT;
    const __half* tileB = g_Vts + ((size_t)(h * 32 + n) * NPADW + n0) * TT;

    float acc[2][8][4];
#pragma unroll
    for (int mt = 0; mt < 2; mt++)
#pragma unroll
        for (int nt = 0; nt < 8; nt++)
#pragma unroll
            for (int i = 0; i < 4; i++) acc[mt][nt][i] = 0.f;

    mm_mainloop<4>(tileA, TT, tileB, TT, smemBase, tid, acc);

    const int lane = tid & 31, w = tid >> 5;
    const int g = lane >> 2, tig = lane & 3;
    const int wm = w & 3, wn = w >> 2;
#pragma unroll
    for (int mt = 0; mt < 2; mt++) {
        int q = m0 + wm * 32 + mt * 16 + g;
#pragma unroll
        for (int nt = 0; nt < 8; nt++) {
            int d = n0 + wn * 64 + nt * 8 + tig * 2;
            if (d < DF) {
                int v = d >> 6;          // d = v*64 + c
                int c = d & 63;          // even
                size_t o = (size_t)n * (512 * TT * NV)
                         + (size_t)((c << 3) + h) * (TT * NV)
                         + (size_t)q * NV + v;
                size_t o2 = o + 8 * TT * NV;          // c+1
                out[o]                = acc[mt][nt][0];
                out[o2]               = acc[mt][nt][1];
                out[o + 8 * NV]       = acc[mt][nt][2];   // q+8
                out[o2 + 8 * NV]      = acc[mt][nt][3];
            }
        }
    }
}

// ---------------- launch ----------------------------------------------------
extern "C" void kernel_launch(void* const* d_in, const int* in_sizes, int n_in,
                              void* d_out, int out_size) {
    const float* x  = (const float*)d_in[0];
    const float* m  = (const float*)d_in[1];
    const float* Wk = (const float*)d_in[2];
    const float* bk = (const float*)d_in[3];
    const float* Wq = (const float*)d_in[4];
    const float* bq = (const float*)d_in[5];
    const float* Wv = (const float*)d_in[6];
    const float* bv = (const float*)d_in[7];
    float* out = (float*)d_out;

    cudaFuncSetAttribute(gemm_proj_mma,   cudaFuncAttributeMaxDynamicSharedMemorySize, SMEM_DYN);
    cudaFuncSetAttribute(gemm_scores_mma, cudaFuncAttributeMaxDynamicSharedMemorySize, SMEM_DYN);
    cudaFuncSetAttribute(gemm_y_mma,      cudaFuncAttributeMaxDynamicSharedMemorySize, SMEM_DYN);

    pack_kernel<<<(MR * DF) / 256, 256>>>(x, 0);
    pack_kernel<<<(MR * DF) / 256, 256>>>(m, 1);
    transpose_w<<<dim3(50, 50, 24), dim3(32, 8)>>>(Wk, Wq, Wv);

    gemm_proj_mma<<<dim3(13, 64, 24), 256, SMEM_DYN>>>(bk, bq, bv);
    transpose_v<<<dim3(8, 50, 256), dim3(32, 8)>>>();

    gemm_scores_mma<<<dim3(2, 2, 256), 256, SMEM_DYN>>>();
    softmax_heads<<<(NBATCH * TT * TT) / 256, 256>>>();
    gemm_y_mma<<<dim3(13, 2, 256), 256, SMEM_DYN>>>(out);
}